// round 11
// baseline (speedup 1.0000x reference)
#include <cuda_runtime.h>
#include <cstdint>
#include <cstddef>

// Shapes (fixed by the problem)
#define B 16
#define W 256
#define S 512
#define H 768
#define L 12
#define E 256

#define LAYER_STRIDE ((size_t)B * S * H)   // elements between layers
#define ROW_BYTES (H * 4)                  // 3072 bytes per (l,b,s) row
#define ROW_F4    (ROW_BYTES / 16)         // 192 float4 per row
#define LH (L / 2)                         // 6 rows per sub-phase
#define PH_BYTES (LH * ROW_BYTES)          // 18432 B per sub-phase
#define MAX_SLOTS (2 * L)                  // up to 24 staged rows
#define SMEM_ROWS_BYTES (MAX_SLOTS * ROW_BYTES)   // 73728
#define SMEM_TOTAL (SMEM_ROWS_BYTES + 64)         // + four mbarriers

__device__ __forceinline__ uint32_t smem_u32(const void* p) {
    return (uint32_t)__cvta_generic_to_shared(p);
}

__device__ __forceinline__ void mbar_wait0(uint32_t mbar) {
    uint32_t done;
    asm volatile(
        "{\n\t.reg .pred p;\n\t"
        "mbarrier.try_wait.parity.acquire.cta.shared::cta.b64 p, [%1], %2, 0x989680;\n\t"
        "selp.b32 %0, 1, 0, p;\n\t}"
        : "=r"(done) : "r"(mbar), "r"(0u) : "memory");
    if (!done) {
        asm volatile(
            "{\n\t.reg .pred P1;\n\t"
            "WL_%=:\n\t"
            "mbarrier.try_wait.parity.acquire.cta.shared::cta.b64 P1, [%0], %1, 0x989680;\n\t"
            "@P1 bra.uni WD_%=;\n\t"
            "bra.uni WL_%=;\n\t"
            "WD_%=:\n\t}"
            :: "r"(mbar), "r"(0u) : "memory");
    }
}

// One block per (b,w) word, 192 threads. Champion structure (R10) with
// 4-way split-phase barriers: each span position's 12 layer-rows are staged
// as two 6-row sub-phases with independent mbarriers, so the block starts
// reducing after the first ~18 KB arrives and overlaps reduce with the
// remaining copies. Threads [0,64) overlap the word-embedding gather.
__global__ __launch_bounds__(192)
void bert_lexer_kernel(const int* __restrict__ word_indices,
                       const int* __restrict__ span_start,
                       const int* __restrict__ span_end,
                       const float* __restrict__ W_embed,
                       const float* __restrict__ hidden,
                       float* __restrict__ out)
{
    extern __shared__ __align__(16) char smem[];
    const uint32_t mb = smem_u32(smem + SMEM_ROWS_BYTES);   // 4 mbarriers, 8 B apart

    const int bw  = blockIdx.x;            // 0 .. B*W-1
    const int b   = bw >> 8;               // W = 256
    const int tid = threadIdx.x;           // 0 .. 191

    const int s0  = span_start[bw];
    const int len = span_end[bw] - s0;     // 1 or 2

    if (tid == 0) {
        #pragma unroll
        for (int k = 0; k < 4; ++k)
            asm volatile("mbarrier.init.shared.b64 [%0], 1;"
                         :: "r"(mb + 8u * k) : "memory");
        asm volatile("fence.proxy.async.shared::cta;" ::: "memory");
    }
    __syncthreads();

    const int nphase = 2 * len;            // 2 or 4 sub-phases

    if (tid == 0) {
        const float* row0 = hidden + ((size_t)b * S + (size_t)s0) * H;
        const uint32_t base = smem_u32(smem);
        // sub-phase ph: span position ph>>1, layers (ph&1)*6 .. +6
        for (int ph = 0; ph < nphase; ++ph) {
            const uint32_t mbar = mb + 8u * ph;
            asm volatile("mbarrier.arrive.expect_tx.shared.b64 _, [%0], %1;"
                         :: "r"(mbar), "n"(PH_BYTES) : "memory");
            const float* src0 = row0 + (size_t)(ph >> 1) * H
                                     + (size_t)((ph & 1) * LH) * LAYER_STRIDE;
            const uint32_t dst0 = base + (uint32_t)ph * PH_BYTES;
            #pragma unroll
            for (int l = 0; l < LH; ++l) {
                asm volatile(
                    "cp.async.bulk.shared::cta.global.mbarrier::complete_tx::bytes "
                    "[%0], [%1], %2, [%3];"
                    :: "r"(dst0 + (uint32_t)l * ROW_BYTES),
                       "l"(src0 + (size_t)l * LAYER_STRIDE),
                       "n"(ROW_BYTES), "r"(mbar) : "memory");
            }
        }
    }

    // ---- overlap: word embedding gather (threads 0..63) ----
    float* orow = out + (size_t)bw * (E + H);
    if (tid < 64) {
        const int wi = word_indices[bw];
        float4 ev = *(reinterpret_cast<const float4*>(W_embed + (size_t)wi * E) + tid);
        __stcs(reinterpret_cast<float4*>(orow) + tid, ev);
    }

    // ---- reduce sub-phase by sub-phase as copies land ----
    const float4* sp = reinterpret_cast<const float4*>(smem) + tid;
    float4 acc = make_float4(0.f, 0.f, 0.f, 0.f);
    for (int ph = 0; ph < nphase; ++ph) {
        mbar_wait0(mb + 8u * ph);
        const float4* spp = sp + (size_t)ph * (PH_BYTES / 16);
        #pragma unroll
        for (int l = 0; l < LH; ++l) {
            float4 v = spp[(size_t)l * ROW_F4];
            acc.x += v.x; acc.y += v.y; acc.z += v.z; acc.w += v.w;
        }
    }

    const float inv = 1.0f / (12.0f * (float)len);
    float4 r;
    r.x = acc.x * inv; r.y = acc.y * inv; r.z = acc.z * inv; r.w = acc.w * inv;
    __stcs(reinterpret_cast<float4*>(orow + E) + tid, r);
}

extern "C" void kernel_launch(void* const* d_in, const int* in_sizes, int n_in,
                              void* d_out, int out_size)
{
    const int*   word_indices = (const int*)  d_in[0];   // [B, W]
    const int*   span_start   = (const int*)  d_in[1];   // [B, W]
    const int*   span_end     = (const int*)  d_in[2];   // [B, W]
    const float* W_embed      = (const float*)d_in[3];   // [V, E]
    const float* hidden       = (const float*)d_in[4];   // [L, B, S, H]
    float*       out          = (float*)      d_out;     // [B, W, E+H]

    (void)in_sizes; (void)n_in; (void)out_size;

    cudaFuncSetAttribute(bert_lexer_kernel,
                         cudaFuncAttributeMaxDynamicSharedMemorySize, SMEM_TOTAL);

    bert_lexer_kernel<<<B * W, 192, SMEM_TOTAL>>>(word_indices, span_start,
                                                  span_end, W_embed, hidden, out);
}

// round 12
// speedup vs baseline: 1.0126x; 1.0126x over previous
#include <cuda_runtime.h>
#include <cstdint>
#include <cstddef>

// Shapes (fixed by the problem)
#define B 16
#define W 256
#define S 512
#define H 768
#define L 12
#define E 256

#define LAYER_STRIDE ((size_t)B * S * H)   // elements between layers
#define ROW_BYTES (H * 4)                  // 3072 bytes per (l,b,s) row
#define ROW_F4    (ROW_BYTES / 16)         // 192 float4 per row
#define MAX_SLOTS (2 * L)                  // up to 24 staged rows
#define SMEM_ROWS_BYTES (MAX_SLOTS * ROW_BYTES)   // 73728
#define SMEM_TOTAL (SMEM_ROWS_BYTES + 32)         // + two mbarriers

__device__ __forceinline__ uint32_t smem_u32(const void* p) {
    return (uint32_t)__cvta_generic_to_shared(p);
}

__device__ __forceinline__ void mbar_wait0(uint32_t mbar) {
    uint32_t done;
    asm volatile(
        "{\n\t.reg .pred p;\n\t"
        "mbarrier.try_wait.parity.acquire.cta.shared::cta.b64 p, [%1], %2, 0x989680;\n\t"
        "selp.b32 %0, 1, 0, p;\n\t}"
        : "=r"(done) : "r"(mbar), "r"(0u) : "memory");
    if (!done) {
        asm volatile(
            "{\n\t.reg .pred P1;\n\t"
            "WL_%=:\n\t"
            "mbarrier.try_wait.parity.acquire.cta.shared::cta.b64 P1, [%0], %1, 0x989680;\n\t"
            "@P1 bra.uni WD_%=;\n\t"
            "bra.uni WL_%=;\n\t"
            "WD_%=:\n\t}"
            :: "r"(mbar), "r"(0u) : "memory");
    }
}

// One block per (b,w) word, 192 threads — R10 champion with scalar-load
// hoisting. span/word-index loads issue BEFORE the init __syncthreads so
// their DRAM/L2 latency hides behind the barrier instead of delaying the
// first cp.async.bulk. Thread 0 stages the span's 12*len rows (3072 B bulk
// copies) with a separate mbarrier per span position; the block reduces
// position 0 while position 1's copies land. Threads [0,64) overlap the
// word-embedding gather.
__global__ __launch_bounds__(192)
void bert_lexer_kernel(const int* __restrict__ word_indices,
                       const int* __restrict__ span_start,
                       const int* __restrict__ span_end,
                       const float* __restrict__ W_embed,
                       const float* __restrict__ hidden,
                       float* __restrict__ out)
{
    extern __shared__ __align__(16) char smem[];
    const uint32_t mbar0 = smem_u32(smem + SMEM_ROWS_BYTES);       // pos 0
    const uint32_t mbar1 = mbar0 + 8;                              // pos 1

    const int bw  = blockIdx.x;            // 0 .. B*W-1
    const int b   = bw >> 8;               // W = 256
    const int tid = threadIdx.x;           // 0 .. 191

    // ---- hoisted scalar loads: latency hides behind the init barrier ----
    const int s0  = span_start[bw];
    const int len = span_end[bw] - s0;     // 1 or 2
    int wi = 0;
    if (tid < 64) wi = word_indices[bw];

    if (tid == 0) {
        asm volatile("mbarrier.init.shared.b64 [%0], 1;" :: "r"(mbar0) : "memory");
        asm volatile("mbarrier.init.shared.b64 [%0], 1;" :: "r"(mbar1) : "memory");
        asm volatile("fence.proxy.async.shared::cta;" ::: "memory");
    }
    __syncthreads();

    if (tid == 0) {
        const float* row0 = hidden + ((size_t)b * S + (size_t)s0) * H;
        const uint32_t base = smem_u32(smem);

        // phase 0: 12 rows of span position s0
        asm volatile("mbarrier.arrive.expect_tx.shared.b64 _, [%0], %1;"
                     :: "r"(mbar0), "n"(L * ROW_BYTES) : "memory");
        #pragma unroll
        for (int l = 0; l < L; ++l) {
            asm volatile(
                "cp.async.bulk.shared::cta.global.mbarrier::complete_tx::bytes "
                "[%0], [%1], %2, [%3];"
                :: "r"(base + (uint32_t)l * ROW_BYTES),
                   "l"(row0 + (size_t)l * LAYER_STRIDE),
                   "n"(ROW_BYTES), "r"(mbar0) : "memory");
        }
        // phase 1: 12 rows of span position s0+1 (len==2 only)
        if (len == 2) {
            asm volatile("mbarrier.arrive.expect_tx.shared.b64 _, [%0], %1;"
                         :: "r"(mbar1), "n"(L * ROW_BYTES) : "memory");
            #pragma unroll
            for (int l = 0; l < L; ++l) {
                asm volatile(
                    "cp.async.bulk.shared::cta.global.mbarrier::complete_tx::bytes "
                    "[%0], [%1], %2, [%3];"
                    :: "r"(base + (uint32_t)(L + l) * ROW_BYTES),
                       "l"(row0 + H + (size_t)l * LAYER_STRIDE),
                       "n"(ROW_BYTES), "r"(mbar1) : "memory");
            }
        }
    }

    // ---- overlap: word embedding gather (threads 0..63) ----
    float* orow = out + (size_t)bw * (E + H);
    if (tid < 64) {
        float4 ev = *(reinterpret_cast<const float4*>(W_embed + (size_t)wi * E) + tid);
        __stcs(reinterpret_cast<float4*>(orow) + tid, ev);
    }

    // ---- phase 0 reduce ----
    mbar_wait0(mbar0);
    const float4* sp = reinterpret_cast<const float4*>(smem) + tid;
    float4 acc = make_float4(0.f, 0.f, 0.f, 0.f);
    #pragma unroll
    for (int l = 0; l < L; ++l) {
        float4 v = sp[(size_t)l * ROW_F4];
        acc.x += v.x; acc.y += v.y; acc.z += v.z; acc.w += v.w;
    }

    // ---- phase 1 reduce (len==2 only) ----
    if (len == 2) {
        mbar_wait0(mbar1);
        const float4* sp1 = sp + (size_t)L * ROW_F4;
        #pragma unroll
        for (int l = 0; l < L; ++l) {
            float4 v = sp1[(size_t)l * ROW_F4];
            acc.x += v.x; acc.y += v.y; acc.z += v.z; acc.w += v.w;
        }
    }

    const float inv = 1.0f / (12.0f * (float)len);
    float4 r;
    r.x = acc.x * inv; r.y = acc.y * inv; r.z = acc.z * inv; r.w = acc.w * inv;
    __stcs(reinterpret_cast<float4*>(orow + E) + tid, r);
}

extern "C" void kernel_launch(void* const* d_in, const int* in_sizes, int n_in,
                              void* d_out, int out_size)
{
    const int*   word_indices = (const int*)  d_in[0];   // [B, W]
    const int*   span_start   = (const int*)  d_in[1];   // [B, W]
    const int*   span_end     = (const int*)  d_in[2];   // [B, W]
    const float* W_embed      = (const float*)d_in[3];   // [V, E]
    const float* hidden       = (const float*)d_in[4];   // [L, B, S, H]
    float*       out          = (float*)      d_out;     // [B, W, E+H]

    (void)in_sizes; (void)n_in; (void)out_size;

    cudaFuncSetAttribute(bert_lexer_kernel,
                         cudaFuncAttributeMaxDynamicSharedMemorySize, SMEM_TOTAL);

    bert_lexer_kernel<<<B * W, 192, SMEM_TOTAL>>>(word_indices, span_start,
                                                  span_end, W_embed, hidden, out);
}

// round 13
// speedup vs baseline: 1.0356x; 1.0227x over previous
#include <cuda_runtime.h>
#include <cstdint>
#include <cstddef>

// Shapes (fixed by the problem)
#define B 16
#define W 256
#define S 512
#define H 768
#define L 12
#define E 256

#define LAYER_STRIDE ((size_t)B * S * H)   // elements between layers
#define ROW_BYTES (H * 4)                  // 3072 bytes per (l,b,s) row
#define ROW_F4    (ROW_BYTES / 16)         // 192 float4 per row
#define MAX_SLOTS (2 * L)                  // up to 24 staged rows
#define SMEM_ROWS_BYTES (MAX_SLOTS * ROW_BYTES)   // 73728
#define SMEM_TOTAL (SMEM_ROWS_BYTES + 32)         // + two mbarriers

__device__ __forceinline__ uint32_t smem_u32(const void* p) {
    return (uint32_t)__cvta_generic_to_shared(p);
}

__device__ __forceinline__ void mbar_wait0(uint32_t mbar) {
    uint32_t done;
    asm volatile(
        "{\n\t.reg .pred p;\n\t"
        "mbarrier.try_wait.parity.acquire.cta.shared::cta.b64 p, [%1], %2, 0x989680;\n\t"
        "selp.b32 %0, 1, 0, p;\n\t}"
        : "=r"(done) : "r"(mbar), "r"(0u) : "memory");
    if (!done) {
        asm volatile(
            "{\n\t.reg .pred P1;\n\t"
            "WL_%=:\n\t"
            "mbarrier.try_wait.parity.acquire.cta.shared::cta.b64 P1, [%0], %1, 0x989680;\n\t"
            "@P1 bra.uni WD_%=;\n\t"
            "bra.uni WL_%=;\n\t"
            "WD_%=:\n\t}"
            :: "r"(mbar), "r"(0u) : "memory");
    }
}

// One block per (b,w) word, 192 threads (R10 champion + parallel phase issue).
// Thread 0 issues phase-0's 12 bulk copies (span position s0); thread 32
// (warp 1) CONCURRENTLY issues phase-1's 12 copies (position s0+1, len==2
// only) on a separate mbarrier. The block reduces position 0 while position
// 1's copies land. Threads [0,64) overlap the word-embedding gather.
__global__ __launch_bounds__(192)
void bert_lexer_kernel(const int* __restrict__ word_indices,
                       const int* __restrict__ span_start,
                       const int* __restrict__ span_end,
                       const float* __restrict__ W_embed,
                       const float* __restrict__ hidden,
                       float* __restrict__ out)
{
    extern __shared__ __align__(16) char smem[];
    const uint32_t mbar0 = smem_u32(smem + SMEM_ROWS_BYTES);       // pos 0
    const uint32_t mbar1 = mbar0 + 8;                              // pos 1

    const int bw  = blockIdx.x;            // 0 .. B*W-1
    const int b   = bw >> 8;               // W = 256
    const int tid = threadIdx.x;           // 0 .. 191

    const int s0  = span_start[bw];
    const int len = span_end[bw] - s0;     // 1 or 2

    if (tid == 0) {
        asm volatile("mbarrier.init.shared.b64 [%0], 1;" :: "r"(mbar0) : "memory");
        asm volatile("mbarrier.init.shared.b64 [%0], 1;" :: "r"(mbar1) : "memory");
        asm volatile("fence.proxy.async.shared::cta;" ::: "memory");
    }
    __syncthreads();

    const float* row0 = hidden + ((size_t)b * S + (size_t)s0) * H;
    const uint32_t base = smem_u32(smem);

    if (tid == 0) {
        // phase 0: 12 rows of span position s0
        asm volatile("mbarrier.arrive.expect_tx.shared.b64 _, [%0], %1;"
                     :: "r"(mbar0), "n"(L * ROW_BYTES) : "memory");
        #pragma unroll
        for (int l = 0; l < L; ++l) {
            asm volatile(
                "cp.async.bulk.shared::cta.global.mbarrier::complete_tx::bytes "
                "[%0], [%1], %2, [%3];"
                :: "r"(base + (uint32_t)l * ROW_BYTES),
                   "l"(row0 + (size_t)l * LAYER_STRIDE),
                   "n"(ROW_BYTES), "r"(mbar0) : "memory");
        }
    } else if (tid == 32 && len == 2) {
        // phase 1 (concurrent, warp 1): 12 rows of span position s0+1
        asm volatile("mbarrier.arrive.expect_tx.shared.b64 _, [%0], %1;"
                     :: "r"(mbar1), "n"(L * ROW_BYTES) : "memory");
        #pragma unroll
        for (int l = 0; l < L; ++l) {
            asm volatile(
                "cp.async.bulk.shared::cta.global.mbarrier::complete_tx::bytes "
                "[%0], [%1], %2, [%3];"
                :: "r"(base + (uint32_t)(L + l) * ROW_BYTES),
                   "l"(row0 + H + (size_t)l * LAYER_STRIDE),
                   "n"(ROW_BYTES), "r"(mbar1) : "memory");
        }
    }

    // ---- overlap: word embedding gather (threads 0..63) ----
    float* orow = out + (size_t)bw * (E + H);
    if (tid < 64) {
        const int wi = word_indices[bw];
        float4 ev = *(reinterpret_cast<const float4*>(W_embed + (size_t)wi * E) + tid);
        __stcs(reinterpret_cast<float4*>(orow) + tid, ev);
    }

    // ---- phase 0 reduce ----
    mbar_wait0(mbar0);
    const float4* sp = reinterpret_cast<const float4*>(smem) + tid;
    float4 acc = make_float4(0.f, 0.f, 0.f, 0.f);
    #pragma unroll
    for (int l = 0; l < L; ++l) {
        float4 v = sp[(size_t)l * ROW_F4];
        acc.x += v.x; acc.y += v.y; acc.z += v.z; acc.w += v.w;
    }

    // ---- phase 1 reduce (len==2 only) ----
    if (len == 2) {
        mbar_wait0(mbar1);
        const float4* sp1 = sp + (size_t)L * ROW_F4;
        #pragma unroll
        for (int l = 0; l < L; ++l) {
            float4 v = sp1[(size_t)l * ROW_F4];
            acc.x += v.x; acc.y += v.y; acc.z += v.z; acc.w += v.w;
        }
    }

    const float inv = 1.0f / (12.0f * (float)len);
    float4 r;
    r.x = acc.x * inv; r.y = acc.y * inv; r.z = acc.z * inv; r.w = acc.w * inv;
    __stcs(reinterpret_cast<float4*>(orow + E) + tid, r);
}

extern "C" void kernel_launch(void* const* d_in, const int* in_sizes, int n_in,
                              void* d_out, int out_size)
{
    const int*   word_indices = (const int*)  d_in[0];   // [B, W]
    const int*   span_start   = (const int*)  d_in[1];   // [B, W]
    const int*   span_end     = (const int*)  d_in[2];   // [B, W]
    const float* W_embed      = (const float*)d_in[3];   // [V, E]
    const float* hidden       = (const float*)d_in[4];   // [L, B, S, H]
    float*       out          = (float*)      d_out;     // [B, W, E+H]

    (void)in_sizes; (void)n_in; (void)out_size;

    cudaFuncSetAttribute(bert_lexer_kernel,
                         cudaFuncAttributeMaxDynamicSharedMemorySize, SMEM_TOTAL);

    bert_lexer_kernel<<<B * W, 192, SMEM_TOTAL>>>(word_indices, span_start,
                                                  span_end, W_embed, hidden, out);
}